// round 16
// baseline (speedup 1.0000x reference)
#include <cuda_runtime.h>
#include <cstdint>

// DialogueSNN: B=32, S=64, V=32000, E=64, H=128, T=20, beta=0.95, thr=1.0
//
// Phase 0 (snn_cur1_kernel): cur1[s][b][h] = fc1(emb) + b1, all tokens.
// Phase 1 (snn_rec_kernel):  1280-step m1 recurrence per (b,h) chain.
// Phase 1b (snn_lists_kernel): mask -> ascending h byte list, padded to 4
//          with sentinel h=128 (zero smem row; +0.0f adds are exact no-ops).
// Phase 2 (snn_seq_kernel): per-(b,v) m2 recurrence; cur2 = one fp32
//          rounding per active h, ascending order (bit-exact, rel_err=0
//          R5-R14). R15/R16: 64-v tiles (33 KB smem), 2 v/thread
//          (LDS.64/entry, same bytes per v), 5 CTA/SM -> 40 warps/SM.
//          Loop body is R13's branch-free unroll-2 form (R14's if-guards
//          regressed via BSSY/BSYNC).

#define BETA 0.95f

__device__ float    g_cur1[64 * 32 * 128];     // 1 MB
__device__ unsigned g_masks[1280 * 32 * 4];
__device__ unsigned g_lists[1280 * 32 * 32];
__device__ int      g_nw[1280 * 32];

// ---------------------------------------------------------------------------
// Kernel 0: cur1 precompute. grid = 64 (s), block = 1024 (8 b x 128 h), 4 passes.
// ---------------------------------------------------------------------------
__global__ void __launch_bounds__(1024)
snn_cur1_kernel(const int* __restrict__ x,
                const float* __restrict__ embed,
                const float* __restrict__ W1,
                const float* __restrict__ b1)
{
    __shared__ float W1s[128 * 64];   // 32 KB
    __shared__ float embs[32 * 64];   // 8 KB

    const int s   = blockIdx.x;
    const int tid = threadIdx.x;

    for (int i = tid; i < 128 * 64; i += 1024) W1s[i] = W1[i];
    for (int i = tid; i < 32 * 64; i += 1024) {
        const int b = i >> 6, e = i & 63;
        const int tok = x[b * 64 + s];
        embs[i] = embed[(size_t)tok * 64 + e];
    }
    __syncthreads();

    const int h  = tid & 127;
    const int bg = tid >> 7;          // 0..7
    const float b1v = b1[h];

    #pragma unroll
    for (int p = 0; p < 4; ++p) {
        const int b = p * 8 + bg;
        float acc = 0.0f;
        #pragma unroll
        for (int e = 0; e < 64; ++e)
            acc = fmaf(embs[b * 64 + e], W1s[h * 64 + e], acc);
        g_cur1[(s * 32 + b) * 128 + h] = acc + b1v;
    }
}

// ---------------------------------------------------------------------------
// Kernel 1: m1 recurrence -> masks. grid = 32 (b), block = 128 (h).
// ---------------------------------------------------------------------------
__global__ void __launch_bounds__(128)
snn_rec_kernel()
{
    const int b    = blockIdx.x;
    const int h    = threadIdx.x;
    const int lane = h & 31;
    const int word = h >> 5;

    float m1  = 0.0f;
    float cur = g_cur1[b * 128 + h];            // s = 0

    #pragma unroll 1
    for (int s = 0; s < 64; ++s) {
        const int sn = (s + 1 < 64) ? (s + 1) : s;
        const float nxt = g_cur1[(sn * 32 + b) * 128 + h];   // prefetch

        #pragma unroll
        for (int t = 0; t < 20; ++t) {
            const float r = (m1 > 1.0f) ? 1.0f : 0.0f;   // reset from pre-update m1
            m1 = fmaf(BETA, m1, cur) - r;
            const unsigned bal = __ballot_sync(0xffffffffu, m1 > 1.0f);
            if (lane == 0)
                g_masks[((s * 20 + t) * 32 + b) * 4 + word] = bal;
        }
        cur = nxt;
    }
}

// ---------------------------------------------------------------------------
// Kernel 1b: mask -> ascending h-index byte list, padded to 4 with h=128.
// ---------------------------------------------------------------------------
__global__ void __launch_bounds__(256)
snn_lists_kernel()
{
    const int idx = blockIdx.x * 256 + threadIdx.x;   // = step*32 + b
    if (idx >= 1280 * 32) return;

    const uint4 mk = *((const uint4*)g_masks + idx);
    unsigned char bytes[128];
    int n = 0;
    unsigned m;
    m = mk.x; while (m) { int h = __ffs(m) - 1; m &= m - 1u; bytes[n++] = (unsigned char)h; }
    m = mk.y; while (m) { int h = __ffs(m) - 1; m &= m - 1u; bytes[n++] = (unsigned char)(h + 32); }
    m = mk.z; while (m) { int h = __ffs(m) - 1; m &= m - 1u; bytes[n++] = (unsigned char)(h + 64); }
    m = mk.w; while (m) { int h = __ffs(m) - 1; m &= m - 1u; bytes[n++] = (unsigned char)(h + 96); }
    while (n & 3) bytes[n++] = 128;   // sentinel -> zero row (exact no-op add)

    const int nw = n >> 2;
    unsigned* dst = g_lists + idx * 32;
    for (int i = 0; i < nw; ++i) {
        dst[i] = (unsigned)bytes[4*i]
               | ((unsigned)bytes[4*i+1] << 8)
               | ((unsigned)bytes[4*i+2] << 16)
               | ((unsigned)bytes[4*i+3] << 24);
    }
    g_nw[idx] = nw;
}

// ---------------------------------------------------------------------------
// Kernel 2: m2 recurrence, bit-exact, 2 v/thread, list-driven (R13 loop form).
// grid = (500 v-tiles, 4 b-groups), block = 256 thr = 8 warps.
// Warp w handles b = blockIdx.y*8 + w over v = vb + 2*lane .. +1.
// Dynamic smem: W2Ts[129][64] floats (row 128 = zeros) = 33024 B, 5 CTA/SM.
// ---------------------------------------------------------------------------
extern __shared__ float W2Ts[];   // 129*64 floats

__global__ void __launch_bounds__(256, 5)
snn_seq_kernel(const float* __restrict__ W2,
               const float* __restrict__ b2,
               float* __restrict__ out)
{
    const int tid  = threadIdx.x;
    const int lane = tid & 31;
    const int b    = blockIdx.y * 8 + (tid >> 5);
    const int vb   = blockIdx.x * 64;

    // Transpose-load the 64-row W2 tile (coalesced GMEM reads).
    for (int i = tid; i < 64 * 128; i += 256) {
        const int v_l = i >> 7;        // 0..63
        const int h   = i & 127;       // 0..127
        W2Ts[h * 64 + v_l] = W2[(size_t)(vb + v_l) * 128 + h];
    }
    if (tid < 64) W2Ts[128 * 64 + tid] = 0.0f;   // sentinel zero row
    __syncthreads();

    const float2 bias = *(const float2*)(b2 + vb + 2 * lane);
    // lane's float2 column base; row h is at p0[h<<5] (row = 32 float2)
    const float2* p0 = (const float2*)W2Ts + lane;

    float2 m2 = make_float2(0.0f, 0.0f);

    #pragma unroll 1
    for (int s = 0; s < 64; ++s) {
        #pragma unroll 1
        for (int t = 0; t < 20; ++t) {
            const int step = s * 20 + t;
            const int idx  = step * 32 + b;
            const int nw   = __ldg(&g_nw[idx]);
            const unsigned* lp = g_lists + idx * 32;

            // ascending h, one rounding per active h per v — bit-exact.
            float2 c = make_float2(0.0f, 0.0f);
            #pragma unroll 2
            for (int i = 0; i < nw; ++i) {
                const unsigned wd = __ldg(lp + i);
                const int h0 =  wd         & 255;
                const int h1 = (wd >> 8)   & 255;
                const int h2 = (wd >> 16)  & 255;
                const int h3 =  wd >> 24;
                const float2 e0 = p0[h0 << 5];
                const float2 e1 = p0[h1 << 5];
                const float2 e2 = p0[h2 << 5];
                const float2 e3 = p0[h3 << 5];
                c.x += e0.x; c.y += e0.y;
                c.x += e1.x; c.y += e1.y;
                c.x += e2.x; c.y += e2.y;
                c.x += e3.x; c.y += e3.y;
            }

            const float cx = c.x + bias.x, cy = c.y + bias.y;

            const float rx = (m2.x > 1.0f) ? 1.0f : 0.0f;
            const float ry = (m2.y > 1.0f) ? 1.0f : 0.0f;
            m2.x = fmaf(BETA, m2.x, cx) - rx;
            m2.y = fmaf(BETA, m2.y, cy) - ry;
        }
        float2 o;
        o.x = (m2.x > 1.0f) ? 1.0f : 0.0f;
        o.y = (m2.y > 1.0f) ? 1.0f : 0.0f;
        *(float2*)(out + ((size_t)(b * 64 + s)) * 32000 + vb + 2 * lane) = o;
    }
}

// ---------------------------------------------------------------------------
extern "C" void kernel_launch(void* const* d_in, const int* in_sizes, int n_in,
                              void* d_out, int out_size)
{
    const int*   x     = (const int*)  d_in[0];
    const float* embed = (const float*)d_in[1];
    const float* W1    = (const float*)d_in[2];
    const float* b1    = (const float*)d_in[3];
    const float* W2    = (const float*)d_in[4];
    const float* b2    = (const float*)d_in[5];
    float* out = (float*)d_out;

    cudaFuncSetAttribute(snn_seq_kernel,
                         cudaFuncAttributeMaxDynamicSharedMemorySize, 33024);

    snn_cur1_kernel<<<64, 1024>>>(x, embed, W1, b1);
    snn_rec_kernel<<<32, 128>>>();
    snn_lists_kernel<<<160, 256>>>();
    snn_seq_kernel<<<dim3(500, 4), 256, 33024>>>(W2, b2, out);
}

// round 17
// speedup vs baseline: 1.2802x; 1.2802x over previous
#include <cuda_runtime.h>
#include <cstdint>

// DialogueSNN: B=32, S=64, V=32000, E=64, H=128, T=20, beta=0.95, thr=1.0
//
// Phase 0 (snn_cur1_kernel): cur1[s][b][h] = fc1(emb) + b1, all tokens.
// Phase 1 (snn_rec_kernel):  1280-step m1 recurrence per (b,h) chain.
// Phase 1b (snn_lists_kernel): mask -> ascending h byte list, padded to 4
//          with sentinel h=128 (zero smem row; +0.0f adds are exact no-ops).
// Phase 2 (snn_seq_kernel): per-(b,v) m2 recurrence; cur2 = one fp32
//          rounding per active h, ascending order (bit-exact, rel_err=0).
//          R17 = R13 shape verbatim (4 v/thread LDS.128, branch-free
//          unroll-2, 1000 quarter-unit CTAs, 66 KB smem, 3 CTA/SM) plus
//          next-step prefetch of nw + first list word to hide the L2-hit
//          latency at every step boundary. (R14 if-guards and R15 2-v/thread
//          both regressed; this is the proven local optimum + one fix.)

#define BETA 0.95f

__device__ float    g_cur1[64 * 32 * 128];     // 1 MB
__device__ unsigned g_masks[1280 * 32 * 4];
__device__ unsigned g_lists[1280 * 32 * 32];
__device__ int      g_nw[1280 * 32];

// ---------------------------------------------------------------------------
// Kernel 0: cur1 precompute. grid = 64 (s), block = 1024 (8 b x 128 h), 4 passes.
// ---------------------------------------------------------------------------
__global__ void __launch_bounds__(1024)
snn_cur1_kernel(const int* __restrict__ x,
                const float* __restrict__ embed,
                const float* __restrict__ W1,
                const float* __restrict__ b1)
{
    __shared__ float W1s[128 * 64];   // 32 KB
    __shared__ float embs[32 * 64];   // 8 KB

    const int s   = blockIdx.x;
    const int tid = threadIdx.x;

    for (int i = tid; i < 128 * 64; i += 1024) W1s[i] = W1[i];
    for (int i = tid; i < 32 * 64; i += 1024) {
        const int b = i >> 6, e = i & 63;
        const int tok = x[b * 64 + s];
        embs[i] = embed[(size_t)tok * 64 + e];
    }
    __syncthreads();

    const int h  = tid & 127;
    const int bg = tid >> 7;          // 0..7
    const float b1v = b1[h];

    #pragma unroll
    for (int p = 0; p < 4; ++p) {
        const int b = p * 8 + bg;
        float acc = 0.0f;
        #pragma unroll
        for (int e = 0; e < 64; ++e)
            acc = fmaf(embs[b * 64 + e], W1s[h * 64 + e], acc);
        g_cur1[(s * 32 + b) * 128 + h] = acc + b1v;
    }
}

// ---------------------------------------------------------------------------
// Kernel 1: m1 recurrence -> masks. grid = 32 (b), block = 128 (h).
// ---------------------------------------------------------------------------
__global__ void __launch_bounds__(128)
snn_rec_kernel()
{
    const int b    = blockIdx.x;
    const int h    = threadIdx.x;
    const int lane = h & 31;
    const int word = h >> 5;

    float m1  = 0.0f;
    float cur = g_cur1[b * 128 + h];            // s = 0

    #pragma unroll 1
    for (int s = 0; s < 64; ++s) {
        const int sn = (s + 1 < 64) ? (s + 1) : s;
        const float nxt = g_cur1[(sn * 32 + b) * 128 + h];   // prefetch

        #pragma unroll
        for (int t = 0; t < 20; ++t) {
            const float r = (m1 > 1.0f) ? 1.0f : 0.0f;   // reset from pre-update m1
            m1 = fmaf(BETA, m1, cur) - r;
            const unsigned bal = __ballot_sync(0xffffffffu, m1 > 1.0f);
            if (lane == 0)
                g_masks[((s * 20 + t) * 32 + b) * 4 + word] = bal;
        }
        cur = nxt;
    }
}

// ---------------------------------------------------------------------------
// Kernel 1b: mask -> ascending h-index byte list, padded to 4 with h=128.
// ---------------------------------------------------------------------------
__global__ void __launch_bounds__(256)
snn_lists_kernel()
{
    const int idx = blockIdx.x * 256 + threadIdx.x;   // = step*32 + b
    if (idx >= 1280 * 32) return;

    const uint4 mk = *((const uint4*)g_masks + idx);
    unsigned char bytes[128];
    int n = 0;
    unsigned m;
    m = mk.x; while (m) { int h = __ffs(m) - 1; m &= m - 1u; bytes[n++] = (unsigned char)h; }
    m = mk.y; while (m) { int h = __ffs(m) - 1; m &= m - 1u; bytes[n++] = (unsigned char)(h + 32); }
    m = mk.z; while (m) { int h = __ffs(m) - 1; m &= m - 1u; bytes[n++] = (unsigned char)(h + 64); }
    m = mk.w; while (m) { int h = __ffs(m) - 1; m &= m - 1u; bytes[n++] = (unsigned char)(h + 96); }
    while (n & 3) bytes[n++] = 128;   // sentinel -> zero row (exact no-op add)

    const int nw = n >> 2;
    unsigned* dst = g_lists + idx * 32;
    for (int i = 0; i < nw; ++i) {
        dst[i] = (unsigned)bytes[4*i]
               | ((unsigned)bytes[4*i+1] << 8)
               | ((unsigned)bytes[4*i+2] << 16)
               | ((unsigned)bytes[4*i+3] << 24);
    }
    g_nw[idx] = nw;
}

// ---------------------------------------------------------------------------
// Kernel 2: m2 recurrence, bit-exact, 4 v/thread, list-driven (R13 shape).
// grid = (250 v-tiles, 4 b-groups), block = 256 thr = 8 warps.
// Warp w handles b = blockIdx.y*8 + w over v = vb + 4*lane .. +3.
// Dynamic smem: W2Ts[129][128] floats (row 128 = zeros) = 66048 B, 3 CTA/SM.
// R17: next-step nw + first-word prefetch carried across the step loop.
// ---------------------------------------------------------------------------
extern __shared__ float W2Ts[];   // 129*128 floats

__global__ void __launch_bounds__(256, 3)
snn_seq_kernel(const float* __restrict__ W2,
               const float* __restrict__ b2,
               float* __restrict__ out)
{
    const int tid  = threadIdx.x;
    const int lane = tid & 31;
    const int b    = blockIdx.y * 8 + (tid >> 5);
    const int vb   = blockIdx.x * 128;

    // Transpose-load the 128-row W2 tile (coalesced GMEM reads).
    for (int i = tid; i < 128 * 128; i += 256) {
        const int v_l = i >> 7;
        const int h   = i & 127;
        W2Ts[h * 128 + v_l] = W2[(size_t)(vb + v_l) * 128 + h];
    }
    if (tid < 128) W2Ts[128 * 128 + tid] = 0.0f;   // sentinel zero row
    __syncthreads();

    const float4 bias = *(const float4*)(b2 + vb + 4 * lane);
    const float4* p0 = (const float4*)W2Ts + lane;

    float4 m2 = make_float4(0.0f, 0.0f, 0.0f, 0.0f);

    // step-0 state prefetched before the loop
    int      nw_c = __ldg(&g_nw[b]);
    unsigned w0_c = __ldg(&g_lists[b * 32]);

    #pragma unroll 1
    for (int s = 0; s < 64; ++s) {
        #pragma unroll 1
        for (int t = 0; t < 20; ++t) {
            const int step  = s * 20 + t;
            const int idx   = step * 32 + b;
            const int nstep = (step + 1 < 1280) ? (step + 1) : step;
            const int nidx  = nstep * 32 + b;

            // prefetch next step's loop bound + first word (hides L2 latency)
            const int      nw_n = __ldg(&g_nw[nidx]);
            const unsigned w0_n = __ldg(&g_lists[nidx * 32]);

            const int nw = nw_c;
            const unsigned* lp = g_lists + idx * 32;

            // ascending h, one rounding per active h per v — bit-exact.
            float4 c = make_float4(0.0f, 0.0f, 0.0f, 0.0f);
            {
                // word 0 from the prefetched register
                const unsigned wd = w0_c;
                const int h0 =  wd         & 255;
                const int h1 = (wd >> 8)   & 255;
                const int h2 = (wd >> 16)  & 255;
                const int h3 =  wd >> 24;
                const float4 e0 = p0[h0 << 5];
                const float4 e1 = p0[h1 << 5];
                const float4 e2 = p0[h2 << 5];
                const float4 e3 = p0[h3 << 5];
                c.x += e0.x; c.y += e0.y; c.z += e0.z; c.w += e0.w;
                c.x += e1.x; c.y += e1.y; c.z += e1.z; c.w += e1.w;
                c.x += e2.x; c.y += e2.y; c.z += e2.z; c.w += e2.w;
                c.x += e3.x; c.y += e3.y; c.z += e3.z; c.w += e3.w;
            }
            #pragma unroll 2
            for (int i = 1; i < nw; ++i) {
                const unsigned wd = __ldg(lp + i);
                const int h0 =  wd         & 255;
                const int h1 = (wd >> 8)   & 255;
                const int h2 = (wd >> 16)  & 255;
                const int h3 =  wd >> 24;
                const float4 e0 = p0[h0 << 5];
                const float4 e1 = p0[h1 << 5];
                const float4 e2 = p0[h2 << 5];
                const float4 e3 = p0[h3 << 5];
                c.x += e0.x; c.y += e0.y; c.z += e0.z; c.w += e0.w;
                c.x += e1.x; c.y += e1.y; c.z += e1.z; c.w += e1.w;
                c.x += e2.x; c.y += e2.y; c.z += e2.z; c.w += e2.w;
                c.x += e3.x; c.y += e3.y; c.z += e3.z; c.w += e3.w;
            }

            const float cx = c.x + bias.x, cy = c.y + bias.y;
            const float cz = c.z + bias.z, cw = c.w + bias.w;

            const float rx = (m2.x > 1.0f) ? 1.0f : 0.0f;
            const float ry = (m2.y > 1.0f) ? 1.0f : 0.0f;
            const float rz = (m2.z > 1.0f) ? 1.0f : 0.0f;
            const float rw = (m2.w > 1.0f) ? 1.0f : 0.0f;
            m2.x = fmaf(BETA, m2.x, cx) - rx;
            m2.y = fmaf(BETA, m2.y, cy) - ry;
            m2.z = fmaf(BETA, m2.z, cz) - rz;
            m2.w = fmaf(BETA, m2.w, cw) - rw;

            nw_c = nw_n;
            w0_c = w0_n;
        }
        float4 o;
        o.x = (m2.x > 1.0f) ? 1.0f : 0.0f;
        o.y = (m2.y > 1.0f) ? 1.0f : 0.0f;
        o.z = (m2.z > 1.0f) ? 1.0f : 0.0f;
        o.w = (m2.w > 1.0f) ? 1.0f : 0.0f;
        *(float4*)(out + ((size_t)(b * 64 + s)) * 32000 + vb + 4 * lane) = o;
    }
}

// ---------------------------------------------------------------------------
extern "C" void kernel_launch(void* const* d_in, const int* in_sizes, int n_in,
                              void* d_out, int out_size)
{
    const int*   x     = (const int*)  d_in[0];
    const float* embed = (const float*)d_in[1];
    const float* W1    = (const float*)d_in[2];
    const float* b1    = (const float*)d_in[3];
    const float* W2    = (const float*)d_in[4];
    const float* b2    = (const float*)d_in[5];
    float* out = (float*)d_out;

    cudaFuncSetAttribute(snn_seq_kernel,
                         cudaFuncAttributeMaxDynamicSharedMemorySize, 66048);

    snn_cur1_kernel<<<64, 1024>>>(x, embed, W1, b1);
    snn_rec_kernel<<<32, 128>>>();
    snn_lists_kernel<<<160, 256>>>();
    snn_seq_kernel<<<dim3(250, 4), 256, 66048>>>(W2, b2, out);
}